// round 1
// baseline (speedup 1.0000x reference)
#include <cuda_runtime.h>
#include <cuda_bf16.h>
#include <math.h>

#define NN 100000
#define NE 1600000
#define NG 32
#define DH 64

// ---------------- scratch (device globals; no allocation allowed) -------------
__device__ int   g_deg[NN];
__device__ float g_dinv[NN];
__device__ int   g_rowptr[NN + 1];
__device__ int   g_cursor[NN];
__device__ int   g_col[NE];
__device__ int   g_bsum[256];
__device__ float g_X1[NN * DH];
__device__ float g_X2[NN * DH];
__device__ float g_H1[NN * DH];
__device__ float g_H2[NN * DH];
__device__ int   g_gbound[NG + 1];
__device__ float g_hg[NG * DH];

// ---------------- degree / CSR build ----------------
__global__ void k_zero_deg() {
    int i = blockIdx.x * blockDim.x + threadIdx.x;
    if (i < NN) g_deg[i] = 0;
}

__global__ void k_hist(const int* __restrict__ dst) {
    int e = blockIdx.x * blockDim.x + threadIdx.x;
    if (e < NE) atomicAdd(&g_deg[dst[e]], 1);
}

__global__ void k_dinv() {
    int i = blockIdx.x * blockDim.x + threadIdx.x;
    if (i < NN) g_dinv[i] = rsqrtf(fmaxf((float)g_deg[i], 1.0f));
}

// per-1024 chunk exclusive scan, chunk totals to g_bsum
__global__ void k_scan1() {
    __shared__ int s[1024];
    int tid = threadIdx.x;
    int i = blockIdx.x * 1024 + tid;
    int v = (i < NN) ? g_deg[i] : 0;
    s[tid] = v;
    __syncthreads();
    for (int off = 1; off < 1024; off <<= 1) {
        int t = (tid >= off) ? s[tid - off] : 0;
        __syncthreads();
        s[tid] += t;
        __syncthreads();
    }
    if (i < NN) g_rowptr[i] = s[tid] - v;      // exclusive, pre-offset
    if (tid == 1023) g_bsum[blockIdx.x] = s[1023];
}

// single block: exclusive scan of 98 chunk sums; total -> rowptr[NN]
__global__ void k_scan2(int nb) {
    __shared__ int s[128];
    int tid = threadIdx.x;
    int v = (tid < nb) ? g_bsum[tid] : 0;
    s[tid] = v;
    __syncthreads();
    for (int off = 1; off < 128; off <<= 1) {
        int t = (tid >= off) ? s[tid - off] : 0;
        __syncthreads();
        s[tid] += t;
        __syncthreads();
    }
    if (tid < nb) g_bsum[tid] = s[tid] - v;    // exclusive
    if (tid == 127) g_rowptr[NN] = s[127];     // grand total (= NE)
}

__global__ void k_scan3() {
    int i = blockIdx.x * blockDim.x + threadIdx.x;
    if (i < NN) {
        int r = g_rowptr[i] + g_bsum[i >> 10];
        g_rowptr[i] = r;
        g_cursor[i] = r;
    }
}

__global__ void k_fill(const int* __restrict__ src, const int* __restrict__ dst) {
    int e = blockIdx.x * blockDim.x + threadIdx.x;
    if (e < NE) {
        int d = dst[e];
        int p = atomicAdd(&g_cursor[d], 1);
        g_col[p] = src[e];
    }
}

// ---------------- SpMM: out = alpha * dinv .* (A (dinv .* x)) + beta * z ------
// 16 threads per node row; float4 lanes over 64 features.
__global__ void k_spmm(const float* __restrict__ x, const float* __restrict__ z,
                       float* __restrict__ out, float alpha, float beta) {
    int node = blockIdx.x * (blockDim.x >> 4) + (threadIdx.x >> 4);
    int lane = threadIdx.x & 15;
    if (node >= NN) return;
    int s = g_rowptr[node];
    int e = g_rowptr[node + 1];
    float4 acc = make_float4(0.f, 0.f, 0.f, 0.f);
    for (int i = s; i < e; i++) {
        int c = g_col[i];
        float dv = g_dinv[c];
        float4 xv = ((const float4*)(x + c * DH))[lane];
        acc.x += dv * xv.x;
        acc.y += dv * xv.y;
        acc.z += dv * xv.z;
        acc.w += dv * xv.w;
    }
    float a = alpha * g_dinv[node];
    float4 r;
    r.x = a * acc.x; r.y = a * acc.y; r.z = a * acc.z; r.w = a * acc.w;
    if (beta != 0.0f) {
        float4 zv = ((const float4*)(z + node * DH))[lane];
        r.x += beta * zv.x; r.y += beta * zv.y;
        r.z += beta * zv.z; r.w += beta * zv.w;
    }
    ((float4*)(out + node * DH))[lane] = r;
}

// ---------------- GEMM: out = [X0|X1|X2] @ W + b (optional relu) --------------
// block: 64 nodes x 64 outputs; blockDim (16,16); 4x4 register microtile.
__global__ void k_gemm(const float* __restrict__ x0, const float* __restrict__ x1,
                       const float* __restrict__ x2,
                       const float* __restrict__ W, const float* __restrict__ b,
                       float* __restrict__ out, int relu) {
    __shared__ float Xs[64 * 65];   // [n][k], padded row 65
    __shared__ float Ws[64 * 64];   // [k][f] for current 64-k part
    int tx = threadIdx.x, ty = threadIdx.y;
    int tid = ty * 16 + tx;
    int n0 = blockIdx.x * 64;

    const float* xp[3] = {x0, x1, x2};
    float acc[4][4] = {};

    for (int p = 0; p < 3; p++) {
        const float* xcur = xp[p];
        // load X tile [64 nodes][64 k] (coalesced reads, padded smem)
        #pragma unroll
        for (int i = 0; i < 16; i++) {
            int li = i * 256 + tid;
            int n = li >> 6, k = li & 63;
            int gn = n0 + n;
            Xs[n * 65 + k] = (gn < NN) ? xcur[gn * DH + k] : 0.f;
        }
        // load W part [64 k][64 f]
        #pragma unroll
        for (int i = 0; i < 16; i++) {
            int li = i * 256 + tid;
            Ws[li] = W[p * 4096 + li];
        }
        __syncthreads();
        #pragma unroll 8
        for (int k = 0; k < 64; k++) {
            float4 wv = *(const float4*)&Ws[k * 64 + tx * 4];
            #pragma unroll
            for (int j = 0; j < 4; j++) {
                float xv = Xs[(ty * 4 + j) * 65 + k];
                acc[j][0] += xv * wv.x;
                acc[j][1] += xv * wv.y;
                acc[j][2] += xv * wv.z;
                acc[j][3] += xv * wv.w;
            }
        }
        __syncthreads();
    }

    float4 bv = *(const float4*)&b[tx * 4];
    #pragma unroll
    for (int j = 0; j < 4; j++) {
        int gn = n0 + ty * 4 + j;
        if (gn < NN) {
            float4 r;
            r.x = acc[j][0] + bv.x;
            r.y = acc[j][1] + bv.y;
            r.z = acc[j][2] + bv.z;
            r.w = acc[j][3] + bv.w;
            if (relu) {
                r.x = fmaxf(r.x, 0.f); r.y = fmaxf(r.y, 0.f);
                r.z = fmaxf(r.z, 0.f); r.w = fmaxf(r.w, 0.f);
            }
            *(float4*)&out[gn * DH + tx * 4] = r;
        }
    }
}

// ---------------- readout ----------------
__global__ void k_bounds(const int* __restrict__ gids) {
    int g = threadIdx.x;
    if (g > NG) return;
    int lo = 0, hi = NN;
    while (lo < hi) {
        int mid = (lo + hi) >> 1;
        if (gids[mid] < g) lo = mid + 1; else hi = mid;
    }
    g_gbound[g] = lo;
}

__global__ void k_pool(const float* __restrict__ h) {
    int g = blockIdx.x;
    int s = g_gbound[g], e = g_gbound[g + 1];
    int f = threadIdx.x & 63, r = threadIdx.x >> 6;  // 256 threads: 4-way over nodes
    float acc = 0.f;
    for (int n = s + r; n < e; n += 4) acc += h[n * DH + f];
    __shared__ float sm[256];
    sm[threadIdx.x] = acc;
    __syncthreads();
    if (r == 0) {
        float v = sm[f] + sm[64 + f] + sm[128 + f] + sm[192 + f];
        float cnt = (float)(e - s);
        g_hg[g * DH + f] = v / fmaxf(cnt, 1.f);
    }
}

__global__ void k_mlp(const float* __restrict__ M0w, const float* __restrict__ M0b,
                      const float* __restrict__ M1w, const float* __restrict__ M1b,
                      const float* __restrict__ M2w, const float* __restrict__ M2b,
                      float* __restrict__ out) {
    __shared__ float h0[NG * 64];
    __shared__ float h1[NG * 32];
    __shared__ float h2[NG * 16];
    int tid = threadIdx.x;
    for (int i = tid; i < NG * 64; i += blockDim.x) h0[i] = g_hg[i];
    __syncthreads();
    if (tid < NG * 32) {
        int g = tid >> 5, f = tid & 31;
        float a = M0b[f];
        #pragma unroll
        for (int k = 0; k < 64; k++) a += h0[g * 64 + k] * M0w[k * 32 + f];
        h1[tid] = fmaxf(a, 0.f);
    }
    __syncthreads();
    if (tid < NG * 16) {
        int g = tid >> 4, f = tid & 15;
        float a = M1b[f];
        #pragma unroll
        for (int k = 0; k < 32; k++) a += h1[g * 32 + k] * M1w[k * 16 + f];
        h2[tid] = fmaxf(a, 0.f);
    }
    __syncthreads();
    if (tid < NG * 3) {
        int g = tid / 3, f = tid % 3;
        float a = M2b[f];
        #pragma unroll
        for (int k = 0; k < 16; k++) a += h2[g * 16 + k] * M2w[k * 3 + f];
        out[tid] = a;
    }
}

// ---------------- launch ----------------
extern "C" void kernel_launch(void* const* d_in, const int* in_sizes, int n_in,
                              void* d_out, int out_size) {
    const float* h    = (const float*)d_in[0];
    const int*   src  = (const int*)d_in[1];
    const int*   dst  = (const int*)d_in[2];
    const int*   gids = (const int*)d_in[3];
    const float* W0   = (const float*)d_in[4];
    const float* b0   = (const float*)d_in[5];
    const float* W1   = (const float*)d_in[6];
    const float* b1   = (const float*)d_in[7];
    const float* W2   = (const float*)d_in[8];
    const float* b2   = (const float*)d_in[9];
    const float* M0w  = (const float*)d_in[10];
    const float* M0b  = (const float*)d_in[11];
    const float* M1w  = (const float*)d_in[12];
    const float* M1b  = (const float*)d_in[13];
    const float* M2w  = (const float*)d_in[14];
    const float* M2b  = (const float*)d_in[15];
    float* out = (float*)d_out;

    float *pX1, *pX2, *pH1, *pH2;
    cudaGetSymbolAddress((void**)&pX1, g_X1);
    cudaGetSymbolAddress((void**)&pX2, g_X2);
    cudaGetSymbolAddress((void**)&pH1, g_H1);
    cudaGetSymbolAddress((void**)&pH2, g_H2);

    const int nb_n = (NN + 255) / 256;
    const int nb_e = (NE + 255) / 256;
    const int nb_scan = (NN + 1023) / 1024;   // 98
    const int nb_spmm = (NN + 15) / 16;       // 6250 (16 nodes/block @256 thr)
    const int nb_gemm = (NN + 63) / 64;       // 1563

    // CSR build
    k_zero_deg<<<nb_n, 256>>>();
    k_hist<<<nb_e, 256>>>(dst);
    k_dinv<<<nb_n, 256>>>();
    k_scan1<<<nb_scan, 1024>>>();
    k_scan2<<<1, 128>>>(nb_scan);
    k_scan3<<<nb_n, 256>>>();
    k_fill<<<nb_e, 256>>>(src, dst);

    dim3 gb(16, 16);

    // layer 0: in = h -> H1 (relu)
    k_spmm<<<nb_spmm, 256>>>(h,   nullptr, pX1, -1.f,  0.f);
    k_spmm<<<nb_spmm, 256>>>(pX1, h,       pX2, -2.f, -1.f);
    k_gemm<<<nb_gemm, gb>>>(h, pX1, pX2, W0, b0, pH1, 1);

    // layer 1: in = H1 -> H2 (relu)
    k_spmm<<<nb_spmm, 256>>>(pH1, nullptr, pX1, -1.f,  0.f);
    k_spmm<<<nb_spmm, 256>>>(pX1, pH1,     pX2, -2.f, -1.f);
    k_gemm<<<nb_gemm, gb>>>(pH1, pX1, pX2, W1, b1, pH2, 1);

    // layer 2: in = H2 -> H1 (no relu)
    k_spmm<<<nb_spmm, 256>>>(pH2, nullptr, pX1, -1.f,  0.f);
    k_spmm<<<nb_spmm, 256>>>(pX1, pH2,     pX2, -2.f, -1.f);
    k_gemm<<<nb_gemm, gb>>>(pH2, pX1, pX2, W2, b2, pH1, 0);

    // readout
    k_bounds<<<1, 64>>>(gids);
    k_pool<<<NG, 256>>>(pH1);
    k_mlp<<<1, 1024>>>(M0w, M0b, M1w, M1b, M2w, M2b, out);
}

// round 2
// speedup vs baseline: 1.2273x; 1.2273x over previous
#include <cuda_runtime.h>
#include <cuda_fp16.h>
#include <math.h>

#define NN 100000
#define NE 1600000
#define NG 32
#define DH 64

typedef unsigned long long ull;

// ---------------- scratch (device globals; no allocation allowed) -------------
__device__ int    g_deg[NN];
__device__ float  g_dinv[NN];
__device__ int    g_rowptr[NN + 1];
__device__ int    g_cursor[NN];
__device__ int    g_col[NE];
__device__ int    g_bsum[256];
__device__ float  g_X1[NN * DH];
__device__ float  g_X2[NN * DH];
__device__ float  g_H1[NN * DH];
__device__ float  g_H2[NN * DH];
__device__ __half g_ys[NN * DH];    // fp16 dinv-scaled gather operand
__device__ __half g_X1s[NN * DH];   // fp16 dinv-scaled X1 for second SpMM
__device__ int    g_gbound[NG + 1];
__device__ float  g_hg[NG * DH];

// ---------------- f32x2 helpers ----------------
__device__ __forceinline__ void fma2(ull& d, ull a, ull b) {
    asm("fma.rn.f32x2 %0, %1, %2, %0;" : "+l"(d) : "l"(a), "l"(b));
}
__device__ __forceinline__ ull pack2(float x, float y) {
    ull r; asm("mov.b64 %0, {%1, %2};" : "=l"(r) : "f"(x), "f"(y)); return r;
}
__device__ __forceinline__ float2 unpack2(ull v) {
    float2 r; asm("mov.b64 {%0, %1}, %2;" : "=f"(r.x), "=f"(r.y) : "l"(v)); return r;
}

// ---------------- degree / CSR build ----------------
__global__ void k_zero_deg() {
    int i = blockIdx.x * blockDim.x + threadIdx.x;
    if (i < NN) g_deg[i] = 0;
}

__global__ void k_hist(const int* __restrict__ dst) {
    int e = blockIdx.x * blockDim.x + threadIdx.x;
    if (e * 4 < NE) {
        int4 d = ((const int4*)dst)[e];
        atomicAdd(&g_deg[d.x], 1);
        atomicAdd(&g_deg[d.y], 1);
        atomicAdd(&g_deg[d.z], 1);
        atomicAdd(&g_deg[d.w], 1);
    }
}

__global__ void k_dinv() {
    int i = blockIdx.x * blockDim.x + threadIdx.x;
    if (i < NN) g_dinv[i] = rsqrtf(fmaxf((float)g_deg[i], 1.0f));
}

__global__ void k_scan1() {
    __shared__ int s[1024];
    int tid = threadIdx.x;
    int i = blockIdx.x * 1024 + tid;
    int v = (i < NN) ? g_deg[i] : 0;
    s[tid] = v;
    __syncthreads();
    for (int off = 1; off < 1024; off <<= 1) {
        int t = (tid >= off) ? s[tid - off] : 0;
        __syncthreads();
        s[tid] += t;
        __syncthreads();
    }
    if (i < NN) g_rowptr[i] = s[tid] - v;
    if (tid == 1023) g_bsum[blockIdx.x] = s[1023];
}

__global__ void k_scan2(int nb) {
    __shared__ int s[128];
    int tid = threadIdx.x;
    int v = (tid < nb) ? g_bsum[tid] : 0;
    s[tid] = v;
    __syncthreads();
    for (int off = 1; off < 128; off <<= 1) {
        int t = (tid >= off) ? s[tid - off] : 0;
        __syncthreads();
        s[tid] += t;
        __syncthreads();
    }
    if (tid < nb) g_bsum[tid] = s[tid] - v;
    if (tid == 127) g_rowptr[NN] = s[127];
}

__global__ void k_scan3() {
    int i = blockIdx.x * blockDim.x + threadIdx.x;
    if (i < NN) {
        int r = g_rowptr[i] + g_bsum[i >> 10];
        g_rowptr[i] = r;
        g_cursor[i] = r;
    }
}

__global__ void k_fill(const int* __restrict__ src, const int* __restrict__ dst) {
    int e = blockIdx.x * blockDim.x + threadIdx.x;
    if (e * 4 < NE) {
        int4 d = ((const int4*)dst)[e];
        int4 s = ((const int4*)src)[e];
        g_col[atomicAdd(&g_cursor[d.x], 1)] = s.x;
        g_col[atomicAdd(&g_cursor[d.y], 1)] = s.y;
        g_col[atomicAdd(&g_cursor[d.z], 1)] = s.z;
        g_col[atomicAdd(&g_cursor[d.w], 1)] = s.w;
    }
}

// ---------------- prescale: ys = (half)(dinv .* x) ----------------
__global__ void k_pre(const float* __restrict__ x, __half* __restrict__ ys) {
    int i = blockIdx.x * blockDim.x + threadIdx.x;   // half2 index, NN*32 total
    if (i < NN * 32) {
        float2 v = ((const float2*)x)[i];
        float di = g_dinv[i >> 5];
        ((__half2*)ys)[i] = __floats2half2_rn(v.x * di, v.y * di);
    }
}

// ---------------- SpMM1: X1 = -dinv.*(A ys);  X1s = (half)(dinv.*X1) ----------
// 8 lanes per node, each lane handles 8 features via one 16B fp16 load per edge.
__global__ void k_spmm1(const __half* __restrict__ ys, float* __restrict__ X1,
                        __half* __restrict__ X1s) {
    int node = blockIdx.x * (blockDim.x >> 3) + (threadIdx.x >> 3);
    int lane = threadIdx.x & 7;
    if (node >= NN) return;
    int s = g_rowptr[node], e = g_rowptr[node + 1];
    const uint4* yp = (const uint4*)ys;
    float a0 = 0.f, a1 = 0.f, a2 = 0.f, a3 = 0.f, a4 = 0.f, a5 = 0.f, a6 = 0.f, a7 = 0.f;
    for (int i = s; i < e; i++) {
        int c = g_col[i];
        uint4 v = yp[c * 8 + lane];
        float2 f0 = __half22float2(*(const __half2*)&v.x);
        float2 f1 = __half22float2(*(const __half2*)&v.y);
        float2 f2 = __half22float2(*(const __half2*)&v.z);
        float2 f3 = __half22float2(*(const __half2*)&v.w);
        a0 += f0.x; a1 += f0.y; a2 += f1.x; a3 += f1.y;
        a4 += f2.x; a5 += f2.y; a6 += f3.x; a7 += f3.y;
    }
    float di = g_dinv[node];
    float s1 = -di;        // X1  = -di * acc
    float s2 = -di * di;   // X1s = di * X1
    float4 r0 = make_float4(s1 * a0, s1 * a1, s1 * a2, s1 * a3);
    float4 r1 = make_float4(s1 * a4, s1 * a5, s1 * a6, s1 * a7);
    ((float4*)(X1 + node * DH))[lane * 2 + 0] = r0;
    ((float4*)(X1 + node * DH))[lane * 2 + 1] = r1;
    uint4 w;
    *(__half2*)&w.x = __floats2half2_rn(s2 * a0, s2 * a1);
    *(__half2*)&w.y = __floats2half2_rn(s2 * a2, s2 * a3);
    *(__half2*)&w.z = __floats2half2_rn(s2 * a4, s2 * a5);
    *(__half2*)&w.w = __floats2half2_rn(s2 * a6, s2 * a7);
    ((uint4*)X1s)[node * 8 + lane] = w;
}

// ---------------- SpMM2: X2 = -2*dinv.*(A X1s) - x0 ---------------------------
__global__ void k_spmm2(const __half* __restrict__ x1s, const float* __restrict__ x0,
                        float* __restrict__ X2) {
    int node = blockIdx.x * (blockDim.x >> 3) + (threadIdx.x >> 3);
    int lane = threadIdx.x & 7;
    if (node >= NN) return;
    int s = g_rowptr[node], e = g_rowptr[node + 1];
    const uint4* yp = (const uint4*)x1s;
    float a0 = 0.f, a1 = 0.f, a2 = 0.f, a3 = 0.f, a4 = 0.f, a5 = 0.f, a6 = 0.f, a7 = 0.f;
    for (int i = s; i < e; i++) {
        int c = g_col[i];
        uint4 v = yp[c * 8 + lane];
        float2 f0 = __half22float2(*(const __half2*)&v.x);
        float2 f1 = __half22float2(*(const __half2*)&v.y);
        float2 f2 = __half22float2(*(const __half2*)&v.z);
        float2 f3 = __half22float2(*(const __half2*)&v.w);
        a0 += f0.x; a1 += f0.y; a2 += f1.x; a3 += f1.y;
        a4 += f2.x; a5 += f2.y; a6 += f3.x; a7 += f3.y;
    }
    float m = -2.f * g_dinv[node];
    float4 z0 = ((const float4*)(x0 + node * DH))[lane * 2 + 0];
    float4 z1 = ((const float4*)(x0 + node * DH))[lane * 2 + 1];
    float4 r0 = make_float4(m * a0 - z0.x, m * a1 - z0.y, m * a2 - z0.z, m * a3 - z0.w);
    float4 r1 = make_float4(m * a4 - z1.x, m * a5 - z1.y, m * a6 - z1.z, m * a7 - z1.w);
    ((float4*)(X2 + node * DH))[lane * 2 + 0] = r0;
    ((float4*)(X2 + node * DH))[lane * 2 + 1] = r1;
}

// ---------------- GEMM: out = [X0|X1|X2] @ W + b (f32x2 packed FMA) -----------
// block: 64 nodes x 64 outputs; (16,16) threads; acc pairs over node dimension.
__global__ void k_gemm(const float* __restrict__ x0, const float* __restrict__ x1,
                       const float* __restrict__ x2,
                       const float* __restrict__ W, const float* __restrict__ bias,
                       float* __restrict__ out, int relu) {
    __shared__ float Xs[64 * 66];   // transposed [k][n], row stride 66 (8B-aligned, low conflict)
    __shared__ float Ws[64 * 64];   // [k][c]
    int tx = threadIdx.x, ty = threadIdx.y;
    int tid = ty * 16 + tx;
    int n0 = blockIdx.x * 64;

    ull acc[4][2];
    #pragma unroll
    for (int c = 0; c < 4; c++) { acc[c][0] = 0ull; acc[c][1] = 0ull; }

    const float* xp[3] = {x0, x1, x2};
    for (int p = 0; p < 3; p++) {
        const float* xc = xp[p];
        // X tile: coalesced float4 loads, transposed scalar stores
        #pragma unroll
        for (int i = 0; i < 4; i++) {
            int li = i * 256 + tid;        // float4 id, 1024 total
            int n = li >> 4;
            int kb = (li & 15) * 4;
            int gn = n0 + n;
            float4 v = (gn < NN) ? ((const float4*)xc)[gn * 16 + (li & 15)]
                                 : make_float4(0.f, 0.f, 0.f, 0.f);
            Xs[(kb + 0) * 66 + n] = v.x;
            Xs[(kb + 1) * 66 + n] = v.y;
            Xs[(kb + 2) * 66 + n] = v.z;
            Xs[(kb + 3) * 66 + n] = v.w;
        }
        // W tile: straight copy
        #pragma unroll
        for (int i = 0; i < 4; i++) {
            int li = i * 256 + tid;
            ((float4*)Ws)[li] = ((const float4*)(W + p * 4096))[li];
        }
        __syncthreads();
        #pragma unroll
        for (int k = 0; k < 64; k++) {
            float4 wv = *(const float4*)&Ws[k * 64 + tx * 4];
            ull xA = *(const ull*)&Xs[k * 66 + ty * 4];       // {n0, n1}
            ull xB = *(const ull*)&Xs[k * 66 + ty * 4 + 2];   // {n2, n3}
            ull w0 = pack2(wv.x, wv.x);
            ull w1 = pack2(wv.y, wv.y);
            ull w2 = pack2(wv.z, wv.z);
            ull w3 = pack2(wv.w, wv.w);
            fma2(acc[0][0], xA, w0); fma2(acc[0][1], xB, w0);
            fma2(acc[1][0], xA, w1); fma2(acc[1][1], xB, w1);
            fma2(acc[2][0], xA, w2); fma2(acc[2][1], xB, w2);
            fma2(acc[3][0], xA, w3); fma2(acc[3][1], xB, w3);
        }
        __syncthreads();
    }

    float4 bv = *(const float4*)&bias[tx * 4];
    #pragma unroll
    for (int p = 0; p < 2; p++) {
        float2 r0 = unpack2(acc[0][p]);
        float2 r1 = unpack2(acc[1][p]);
        float2 r2 = unpack2(acc[2][p]);
        float2 r3 = unpack2(acc[3][p]);
        int gn = n0 + ty * 4 + 2 * p;
        if (gn < NN) {
            float4 o = make_float4(r0.x + bv.x, r1.x + bv.y, r2.x + bv.z, r3.x + bv.w);
            if (relu) { o.x = fmaxf(o.x, 0.f); o.y = fmaxf(o.y, 0.f); o.z = fmaxf(o.z, 0.f); o.w = fmaxf(o.w, 0.f); }
            *(float4*)&out[gn * DH + tx * 4] = o;
        }
        if (gn + 1 < NN) {
            float4 o = make_float4(r0.y + bv.x, r1.y + bv.y, r2.y + bv.z, r3.y + bv.w);
            if (relu) { o.x = fmaxf(o.x, 0.f); o.y = fmaxf(o.y, 0.f); o.z = fmaxf(o.z, 0.f); o.w = fmaxf(o.w, 0.f); }
            *(float4*)&out[(gn + 1) * DH + tx * 4] = o;
        }
    }
}

// ---------------- readout ----------------
__global__ void k_bounds(const int* __restrict__ gids) {
    int g = threadIdx.x;
    if (g > NG) return;
    int lo = 0, hi = NN;
    while (lo < hi) {
        int mid = (lo + hi) >> 1;
        if (gids[mid] < g) lo = mid + 1; else hi = mid;
    }
    g_gbound[g] = lo;
}

__global__ void k_pool(const float* __restrict__ h) {
    int g = blockIdx.x;
    int s = g_gbound[g], e = g_gbound[g + 1];
    int f = threadIdx.x & 63, r = threadIdx.x >> 6;
    float acc = 0.f;
    for (int n = s + r; n < e; n += 4) acc += h[n * DH + f];
    __shared__ float sm[256];
    sm[threadIdx.x] = acc;
    __syncthreads();
    if (r == 0) {
        float v = sm[f] + sm[64 + f] + sm[128 + f] + sm[192 + f];
        float cnt = (float)(e - s);
        g_hg[g * DH + f] = v / fmaxf(cnt, 1.f);
    }
}

__global__ void k_mlp(const float* __restrict__ M0w, const float* __restrict__ M0b,
                      const float* __restrict__ M1w, const float* __restrict__ M1b,
                      const float* __restrict__ M2w, const float* __restrict__ M2b,
                      float* __restrict__ out) {
    __shared__ float h0[NG * 64];
    __shared__ float h1[NG * 32];
    __shared__ float h2[NG * 16];
    int tid = threadIdx.x;
    for (int i = tid; i < NG * 64; i += blockDim.x) h0[i] = g_hg[i];
    __syncthreads();
    if (tid < NG * 32) {
        int g = tid >> 5, f = tid & 31;
        float a = M0b[f];
        #pragma unroll
        for (int k = 0; k < 64; k++) a += h0[g * 64 + k] * M0w[k * 32 + f];
        h1[tid] = fmaxf(a, 0.f);
    }
    __syncthreads();
    if (tid < NG * 16) {
        int g = tid >> 4, f = tid & 15;
        float a = M1b[f];
        #pragma unroll
        for (int k = 0; k < 32; k++) a += h1[g * 32 + k] * M1w[k * 16 + f];
        h2[tid] = fmaxf(a, 0.f);
    }
    __syncthreads();
    if (tid < NG * 3) {
        int g = tid / 3, f = tid % 3;
        float a = M2b[f];
        #pragma unroll
        for (int k = 0; k < 16; k++) a += h2[g * 16 + k] * M2w[k * 3 + f];
        out[tid] = a;
    }
}

// ---------------- launch ----------------
extern "C" void kernel_launch(void* const* d_in, const int* in_sizes, int n_in,
                              void* d_out, int out_size) {
    const float* h    = (const float*)d_in[0];
    const int*   src  = (const int*)d_in[1];
    const int*   dst  = (const int*)d_in[2];
    const int*   gids = (const int*)d_in[3];
    const float* W0   = (const float*)d_in[4];
    const float* b0   = (const float*)d_in[5];
    const float* W1   = (const float*)d_in[6];
    const float* b1   = (const float*)d_in[7];
    const float* W2   = (const float*)d_in[8];
    const float* b2   = (const float*)d_in[9];
    const float* M0w  = (const float*)d_in[10];
    const float* M0b  = (const float*)d_in[11];
    const float* M1w  = (const float*)d_in[12];
    const float* M1b  = (const float*)d_in[13];
    const float* M2w  = (const float*)d_in[14];
    const float* M2b  = (const float*)d_in[15];
    float* out = (float*)d_out;

    float *pX1, *pX2, *pH1, *pH2;
    __half *pYs, *pX1s;
    cudaGetSymbolAddress((void**)&pX1, g_X1);
    cudaGetSymbolAddress((void**)&pX2, g_X2);
    cudaGetSymbolAddress((void**)&pH1, g_H1);
    cudaGetSymbolAddress((void**)&pH2, g_H2);
    cudaGetSymbolAddress((void**)&pYs, g_ys);
    cudaGetSymbolAddress((void**)&pX1s, g_X1s);

    const int nb_n = (NN + 255) / 256;
    const int nb_e4 = (NE / 4 + 255) / 256;
    const int nb_scan = (NN + 1023) / 1024;
    const int nb_spmm = (NN + 31) / 32;       // 32 nodes/block @ 256 thr, 8 lanes/node
    const int nb_gemm = (NN + 63) / 64;
    const int nb_pre = (NN * 32 + 255) / 256;

    // CSR build
    k_zero_deg<<<nb_n, 256>>>();
    k_hist<<<nb_e4, 256>>>(dst);
    k_dinv<<<nb_n, 256>>>();
    k_scan1<<<nb_scan, 1024>>>();
    k_scan2<<<1, 128>>>(nb_scan);
    k_scan3<<<nb_n, 256>>>();
    k_fill<<<nb_e4, 256>>>(src, dst);

    dim3 gb(16, 16);

    // layer 0
    k_pre<<<nb_pre, 256>>>(h, pYs);
    k_spmm1<<<nb_spmm, 256>>>(pYs, pX1, pX1s);
    k_spmm2<<<nb_spmm, 256>>>(pX1s, h, pX2);
    k_gemm<<<nb_gemm, gb>>>(h, pX1, pX2, W0, b0, pH1, 1);

    // layer 1
    k_pre<<<nb_pre, 256>>>(pH1, pYs);
    k_spmm1<<<nb_spmm, 256>>>(pYs, pX1, pX1s);
    k_spmm2<<<nb_spmm, 256>>>(pX1s, pH1, pX2);
    k_gemm<<<nb_gemm, gb>>>(pH1, pX1, pX2, W1, b1, pH2, 1);

    // layer 2 (no relu)
    k_pre<<<nb_pre, 256>>>(pH2, pYs);
    k_spmm1<<<nb_spmm, 256>>>(pYs, pX1, pX1s);
    k_spmm2<<<nb_spmm, 256>>>(pX1s, pH2, pX2);
    k_gemm<<<nb_gemm, gb>>>(pH2, pX1, pX2, W2, b2, pH1, 0);

    // readout
    k_bounds<<<1, 64>>>(gids);
    k_pool<<<NG, 256>>>(pH1);
    k_mlp<<<1, 1024>>>(M0w, M0b, M1w, M1b, M2w, M2b, out);
}

// round 3
// speedup vs baseline: 2.0236x; 1.6489x over previous
#include <cuda_runtime.h>
#include <cuda_fp16.h>
#include <math.h>
#include <stdint.h>

#define NN 100000
#define NE 1600000
#define NG 32
#define DH 64

// ---------------- scratch (device globals; no allocation allowed) -------------
__device__ int    g_deg[NN];
__device__ float  g_dinv[NN];
__device__ int    g_rowptr[NN + 1];
__device__ int    g_cursor[NN];
__device__ int    g_col[NE];
__device__ int    g_bsum[256];
__device__ __half g_hh[NN * DH];    // fp16 unscaled features (X0 for GEMM, z for spmm2)
__device__ __half g_hs[NN * DH];    // fp16 dinv-scaled features (gather operand)
__device__ __half g_x1h[NN * DH];   // fp16 X1 (for GEMM)
__device__ __half g_x1s[NN * DH];   // fp16 dinv-scaled X1 (gather operand spmm2)
__device__ __half g_x2h[NN * DH];   // fp16 X2 (for GEMM)
__device__ float  g_H1[NN * DH];    // fp32 final-layer output (for pooling)
__device__ int    g_gbound[NG + 1];
__device__ float  g_hg[NG * DH];

// ---------------- mma helpers ----------------
__device__ __forceinline__ uint32_t smem_u32(const void* p) {
    return (uint32_t)__cvta_generic_to_shared(p);
}
__device__ __forceinline__ void ldmx4(uint32_t* r, uint32_t addr) {
    asm volatile("ldmatrix.sync.aligned.m8n8.x4.shared.b16 {%0,%1,%2,%3}, [%4];"
                 : "=r"(r[0]), "=r"(r[1]), "=r"(r[2]), "=r"(r[3]) : "r"(addr));
}
__device__ __forceinline__ void ldmx4t(uint32_t* r, uint32_t addr) {
    asm volatile("ldmatrix.sync.aligned.m8n8.x4.trans.shared.b16 {%0,%1,%2,%3}, [%4];"
                 : "=r"(r[0]), "=r"(r[1]), "=r"(r[2]), "=r"(r[3]) : "r"(addr));
}
__device__ __forceinline__ void mma16816(float* c, const uint32_t* a, const uint32_t* b) {
    asm volatile("mma.sync.aligned.m16n8k16.row.col.f32.f16.f16.f32 "
                 "{%0,%1,%2,%3}, {%4,%5,%6,%7}, {%8,%9}, {%0,%1,%2,%3};"
                 : "+f"(c[0]), "+f"(c[1]), "+f"(c[2]), "+f"(c[3])
                 : "r"(a[0]), "r"(a[1]), "r"(a[2]), "r"(a[3]), "r"(b[0]), "r"(b[1]));
}

// ---------------- degree / CSR build ----------------
__global__ void k_zero_deg() {
    int i = blockIdx.x * blockDim.x + threadIdx.x;
    if (i < NN) g_deg[i] = 0;
}

__global__ void k_hist(const int* __restrict__ dst) {
    int e = blockIdx.x * blockDim.x + threadIdx.x;
    if (e * 4 < NE) {
        int4 d = ((const int4*)dst)[e];
        atomicAdd(&g_deg[d.x], 1);
        atomicAdd(&g_deg[d.y], 1);
        atomicAdd(&g_deg[d.z], 1);
        atomicAdd(&g_deg[d.w], 1);
    }
}

__global__ void k_dinv() {
    int i = blockIdx.x * blockDim.x + threadIdx.x;
    if (i < NN) g_dinv[i] = rsqrtf(fmaxf((float)g_deg[i], 1.0f));
}

__global__ void k_scan1() {
    __shared__ int s[1024];
    int tid = threadIdx.x;
    int i = blockIdx.x * 1024 + tid;
    int v = (i < NN) ? g_deg[i] : 0;
    s[tid] = v;
    __syncthreads();
    for (int off = 1; off < 1024; off <<= 1) {
        int t = (tid >= off) ? s[tid - off] : 0;
        __syncthreads();
        s[tid] += t;
        __syncthreads();
    }
    if (i < NN) g_rowptr[i] = s[tid] - v;
    if (tid == 1023) g_bsum[blockIdx.x] = s[1023];
}

__global__ void k_scan2(int nb) {
    __shared__ int s[128];
    int tid = threadIdx.x;
    int v = (tid < nb) ? g_bsum[tid] : 0;
    s[tid] = v;
    __syncthreads();
    for (int off = 1; off < 128; off <<= 1) {
        int t = (tid >= off) ? s[tid - off] : 0;
        __syncthreads();
        s[tid] += t;
        __syncthreads();
    }
    if (tid < nb) g_bsum[tid] = s[tid] - v;
    if (tid == 127) g_rowptr[NN] = s[127];
}

__global__ void k_scan3() {
    int i = blockIdx.x * blockDim.x + threadIdx.x;
    if (i < NN) {
        int r = g_rowptr[i] + g_bsum[i >> 10];
        g_rowptr[i] = r;
        g_cursor[i] = r;
    }
}

__global__ void k_fill(const int* __restrict__ src, const int* __restrict__ dst) {
    int e = blockIdx.x * blockDim.x + threadIdx.x;
    if (e * 4 < NE) {
        int4 d = ((const int4*)dst)[e];
        int4 s = ((const int4*)src)[e];
        g_col[atomicAdd(&g_cursor[d.x], 1)] = s.x;
        g_col[atomicAdd(&g_cursor[d.y], 1)] = s.y;
        g_col[atomicAdd(&g_cursor[d.z], 1)] = s.z;
        g_col[atomicAdd(&g_cursor[d.w], 1)] = s.w;
    }
}

// ---------------- prescale (layer 0 only): hs = half(dinv.*x), hh = half(x) ---
__global__ void k_pre(const float* __restrict__ x) {
    int i = blockIdx.x * blockDim.x + threadIdx.x;   // half2 index
    if (i < NN * 32) {
        float2 v = ((const float2*)x)[i];
        float di = g_dinv[i >> 5];
        ((__half2*)g_hs)[i] = __floats2half2_rn(v.x * di, v.y * di);
        ((__half2*)g_hh)[i] = __floats2half2_rn(v.x, v.y);
    }
}

// ---------------- SpMM1: X1h = half(-dinv.*(A hs)); X1s = half(dinv.*X1) ------
__global__ void k_spmm1(const __half* __restrict__ ys, __half* __restrict__ X1h,
                        __half* __restrict__ X1s) {
    int node = blockIdx.x * (blockDim.x >> 3) + (threadIdx.x >> 3);
    int lane = threadIdx.x & 7;
    if (node >= NN) return;
    int s = g_rowptr[node], e = g_rowptr[node + 1];
    const uint4* yp = (const uint4*)ys;
    float a0 = 0.f, a1 = 0.f, a2 = 0.f, a3 = 0.f, a4 = 0.f, a5 = 0.f, a6 = 0.f, a7 = 0.f;
    for (int i = s; i < e; i++) {
        int c = g_col[i];
        uint4 v = yp[c * 8 + lane];
        float2 f0 = __half22float2(*(const __half2*)&v.x);
        float2 f1 = __half22float2(*(const __half2*)&v.y);
        float2 f2 = __half22float2(*(const __half2*)&v.z);
        float2 f3 = __half22float2(*(const __half2*)&v.w);
        a0 += f0.x; a1 += f0.y; a2 += f1.x; a3 += f1.y;
        a4 += f2.x; a5 += f2.y; a6 += f3.x; a7 += f3.y;
    }
    float di = g_dinv[node];
    float s1 = -di;
    float s2 = -di * di;
    uint4 w1, w2;
    *(__half2*)&w1.x = __floats2half2_rn(s1 * a0, s1 * a1);
    *(__half2*)&w1.y = __floats2half2_rn(s1 * a2, s1 * a3);
    *(__half2*)&w1.z = __floats2half2_rn(s1 * a4, s1 * a5);
    *(__half2*)&w1.w = __floats2half2_rn(s1 * a6, s1 * a7);
    *(__half2*)&w2.x = __floats2half2_rn(s2 * a0, s2 * a1);
    *(__half2*)&w2.y = __floats2half2_rn(s2 * a2, s2 * a3);
    *(__half2*)&w2.z = __floats2half2_rn(s2 * a4, s2 * a5);
    *(__half2*)&w2.w = __floats2half2_rn(s2 * a6, s2 * a7);
    ((uint4*)X1h)[node * 8 + lane] = w1;
    ((uint4*)X1s)[node * 8 + lane] = w2;
}

// ---------------- SpMM2: X2h = half(-2*dinv.*(A X1s) - hh) --------------------
__global__ void k_spmm2(const __half* __restrict__ x1s, const __half* __restrict__ z,
                        __half* __restrict__ X2h) {
    int node = blockIdx.x * (blockDim.x >> 3) + (threadIdx.x >> 3);
    int lane = threadIdx.x & 7;
    if (node >= NN) return;
    int s = g_rowptr[node], e = g_rowptr[node + 1];
    const uint4* yp = (const uint4*)x1s;
    float a0 = 0.f, a1 = 0.f, a2 = 0.f, a3 = 0.f, a4 = 0.f, a5 = 0.f, a6 = 0.f, a7 = 0.f;
    for (int i = s; i < e; i++) {
        int c = g_col[i];
        uint4 v = yp[c * 8 + lane];
        float2 f0 = __half22float2(*(const __half2*)&v.x);
        float2 f1 = __half22float2(*(const __half2*)&v.y);
        float2 f2 = __half22float2(*(const __half2*)&v.z);
        float2 f3 = __half22float2(*(const __half2*)&v.w);
        a0 += f0.x; a1 += f0.y; a2 += f1.x; a3 += f1.y;
        a4 += f2.x; a5 += f2.y; a6 += f3.x; a7 += f3.y;
    }
    float m = -2.f * g_dinv[node];
    uint4 zv = ((const uint4*)z)[node * 8 + lane];
    float2 z0 = __half22float2(*(const __half2*)&zv.x);
    float2 z1 = __half22float2(*(const __half2*)&zv.y);
    float2 z2 = __half22float2(*(const __half2*)&zv.z);
    float2 z3 = __half22float2(*(const __half2*)&zv.w);
    uint4 w;
    *(__half2*)&w.x = __floats2half2_rn(m * a0 - z0.x, m * a1 - z0.y);
    *(__half2*)&w.y = __floats2half2_rn(m * a2 - z1.x, m * a3 - z1.y);
    *(__half2*)&w.z = __floats2half2_rn(m * a4 - z2.x, m * a5 - z2.y);
    *(__half2*)&w.w = __floats2half2_rn(m * a6 - z3.x, m * a7 - z3.y);
    ((uint4*)X2h)[node * 8 + lane] = w;
}

// ---------------- GEMM (HMMA): out = [X0|X1|X2] @ W + b -----------------------
// block: 128 nodes x 64 outputs; 128 threads (4 warps, 32 nodes each).
// Epilogue writes: fp32 (final layer) OR fp16 unscaled + fp16 dinv-scaled.
__global__ void k_gemm(const __half* __restrict__ x0, const __half* __restrict__ x1,
                       const __half* __restrict__ x2,
                       const float* __restrict__ W, const float* __restrict__ bias,
                       float* __restrict__ outF, __half* __restrict__ outH,
                       __half* __restrict__ outS, int relu, int wf32) {
    __shared__ __align__(16) __half Xs[128 * 72];
    __shared__ __align__(16) __half Ws[64 * 72];
    int tid = threadIdx.x;
    int warp = tid >> 5, lane = tid & 31;
    int n0 = blockIdx.x * 128;

    float acc[2][8][4];
    #pragma unroll
    for (int tm = 0; tm < 2; tm++)
        #pragma unroll
        for (int nt = 0; nt < 8; nt++)
            #pragma unroll
            for (int q = 0; q < 4; q++) acc[tm][nt][q] = 0.f;

    const __half* xp[3] = {x0, x1, x2};
    for (int p = 0; p < 3; p++) {
        const __half* xc = xp[p];
        // X tile: 128 rows x 64 halves (uint4 = 8 halves), 1024 uint4 / 128 thr
        #pragma unroll
        for (int i = 0; i < 8; i++) {
            int li = i * 128 + tid;
            int row = li >> 3, c = li & 7;
            int gn = n0 + row;
            uint4 v = (gn < NN) ? ((const uint4*)xc)[gn * 8 + c]
                                : make_uint4(0u, 0u, 0u, 0u);
            *(uint4*)&Xs[row * 72 + c * 8] = v;
        }
        // W tile: 64x64 fp32 -> fp16
        #pragma unroll
        for (int i = 0; i < 8; i++) {
            int li = i * 128 + tid;          // float4 id
            int row = li >> 4, c = li & 15;
            float4 w = ((const float4*)(W + p * 4096))[li];
            __half2 h01 = __floats2half2_rn(w.x, w.y);
            __half2 h23 = __floats2half2_rn(w.z, w.w);
            uint2 pk;
            pk.x = *(uint32_t*)&h01;
            pk.y = *(uint32_t*)&h23;
            *(uint2*)&Ws[row * 72 + c * 4] = pk;
        }
        __syncthreads();
        #pragma unroll
        for (int ks = 0; ks < 4; ks++) {
            int kb = ks * 16;
            uint32_t A[2][4];
            #pragma unroll
            for (int tm = 0; tm < 2; tm++) {
                int r = warp * 32 + tm * 16 + (lane & 15);
                ldmx4(A[tm], smem_u32(&Xs[r * 72 + kb + (lane >> 4) * 8]));
            }
            uint32_t B[8][2];
            #pragma unroll
            for (int g = 0; g < 4; g++) {
                uint32_t t[4];
                int krow = kb + (lane & 15);
                ldmx4t(t, smem_u32(&Ws[krow * 72 + g * 16 + (lane >> 4) * 8]));
                B[g * 2 + 0][0] = t[0]; B[g * 2 + 0][1] = t[1];
                B[g * 2 + 1][0] = t[2]; B[g * 2 + 1][1] = t[3];
            }
            #pragma unroll
            for (int tm = 0; tm < 2; tm++)
                #pragma unroll
                for (int nt = 0; nt < 8; nt++)
                    mma16816(acc[tm][nt], A[tm], B[nt]);
        }
        __syncthreads();
    }

    // epilogue
    int col = 2 * (lane & 3);
    #pragma unroll
    for (int tm = 0; tm < 2; tm++) {
        #pragma unroll
        for (int hh = 0; hh < 2; hh++) {
            int node = n0 + warp * 32 + tm * 16 + (lane >> 2) + hh * 8;
            if (node >= NN) continue;
            float di = g_dinv[node];
            #pragma unroll
            for (int nt = 0; nt < 8; nt++) {
                int f = nt * 8 + col;
                float2 bv = *(const float2*)&bias[f];
                float v0 = acc[tm][nt][hh * 2 + 0] + bv.x;
                float v1 = acc[tm][nt][hh * 2 + 1] + bv.y;
                if (relu) { v0 = fmaxf(v0, 0.f); v1 = fmaxf(v1, 0.f); }
                if (wf32) {
                    *(float2*)&outF[node * DH + f] = make_float2(v0, v1);
                } else {
                    *(__half2*)&outH[node * DH + f] = __floats2half2_rn(v0, v1);
                    *(__half2*)&outS[node * DH + f] = __floats2half2_rn(v0 * di, v1 * di);
                }
            }
        }
    }
}

// ---------------- readout ----------------
__global__ void k_bounds(const int* __restrict__ gids) {
    int g = threadIdx.x;
    if (g > NG) return;
    int lo = 0, hi = NN;
    while (lo < hi) {
        int mid = (lo + hi) >> 1;
        if (gids[mid] < g) lo = mid + 1; else hi = mid;
    }
    g_gbound[g] = lo;
}

__global__ void k_pool(const float* __restrict__ h) {
    int g = blockIdx.x;
    int s = g_gbound[g], e = g_gbound[g + 1];
    int f = threadIdx.x & 63, r = threadIdx.x >> 6;
    float acc = 0.f;
    for (int n = s + r; n < e; n += 4) acc += h[n * DH + f];
    __shared__ float sm[256];
    sm[threadIdx.x] = acc;
    __syncthreads();
    if (r == 0) {
        float v = sm[f] + sm[64 + f] + sm[128 + f] + sm[192 + f];
        float cnt = (float)(e - s);
        g_hg[g * DH + f] = v / fmaxf(cnt, 1.f);
    }
}

__global__ void k_mlp(const float* __restrict__ M0w, const float* __restrict__ M0b,
                      const float* __restrict__ M1w, const float* __restrict__ M1b,
                      const float* __restrict__ M2w, const float* __restrict__ M2b,
                      float* __restrict__ out) {
    __shared__ float h0[NG * 64];
    __shared__ float h1[NG * 32];
    __shared__ float h2[NG * 16];
    int tid = threadIdx.x;
    for (int i = tid; i < NG * 64; i += blockDim.x) h0[i] = g_hg[i];
    __syncthreads();
    if (tid < NG * 32) {
        int g = tid >> 5, f = tid & 31;
        float a = M0b[f];
        #pragma unroll
        for (int k = 0; k < 64; k++) a += h0[g * 64 + k] * M0w[k * 32 + f];
        h1[tid] = fmaxf(a, 0.f);
    }
    __syncthreads();
    if (tid < NG * 16) {
        int g = tid >> 4, f = tid & 15;
        float a = M1b[f];
        #pragma unroll
        for (int k = 0; k < 32; k++) a += h1[g * 32 + k] * M1w[k * 16 + f];
        h2[tid] = fmaxf(a, 0.f);
    }
    __syncthreads();
    if (tid < NG * 3) {
        int g = tid / 3, f = tid % 3;
        float a = M2b[f];
        #pragma unroll
        for (int k = 0; k < 16; k++) a += h2[g * 16 + k] * M2w[k * 3 + f];
        out[tid] = a;
    }
}

// ---------------- launch ----------------
extern "C" void kernel_launch(void* const* d_in, const int* in_sizes, int n_in,
                              void* d_out, int out_size) {
    const float* h    = (const float*)d_in[0];
    const int*   src  = (const int*)d_in[1];
    const int*   dst  = (const int*)d_in[2];
    const int*   gids = (const int*)d_in[3];
    const float* W0   = (const float*)d_in[4];
    const float* b0   = (const float*)d_in[5];
    const float* W1   = (const float*)d_in[6];
    const float* b1   = (const float*)d_in[7];
    const float* W2   = (const float*)d_in[8];
    const float* b2   = (const float*)d_in[9];
    const float* M0w  = (const float*)d_in[10];
    const float* M0b  = (const float*)d_in[11];
    const float* M1w  = (const float*)d_in[12];
    const float* M1b  = (const float*)d_in[13];
    const float* M2w  = (const float*)d_in[14];
    const float* M2b  = (const float*)d_in[15];
    float* out = (float*)d_out;

    float *pH1;
    __half *pHh, *pHs, *pX1h, *pX1s, *pX2h;
    cudaGetSymbolAddress((void**)&pH1, g_H1);
    cudaGetSymbolAddress((void**)&pHh, g_hh);
    cudaGetSymbolAddress((void**)&pHs, g_hs);
    cudaGetSymbolAddress((void**)&pX1h, g_x1h);
    cudaGetSymbolAddress((void**)&pX1s, g_x1s);
    cudaGetSymbolAddress((void**)&pX2h, g_x2h);

    const int nb_n = (NN + 255) / 256;
    const int nb_e4 = (NE / 4 + 255) / 256;
    const int nb_scan = (NN + 1023) / 1024;
    const int nb_spmm = (NN + 31) / 32;
    const int nb_gemm = (NN + 127) / 128;
    const int nb_pre = (NN * 32 + 255) / 256;

    // CSR build
    k_zero_deg<<<nb_n, 256>>>();
    k_hist<<<nb_e4, 256>>>(dst);
    k_dinv<<<nb_n, 256>>>();
    k_scan1<<<nb_scan, 1024>>>();
    k_scan2<<<1, 128>>>(nb_scan);
    k_scan3<<<nb_n, 256>>>();
    k_fill<<<nb_e4, 256>>>(src, dst);

    // layer 0
    k_pre<<<nb_pre, 256>>>(h);
    k_spmm1<<<nb_spmm, 256>>>(pHs, pX1h, pX1s);
    k_spmm2<<<nb_spmm, 256>>>(pX1s, pHh, pX2h);
    k_gemm<<<nb_gemm, 128>>>(pHh, pX1h, pX2h, W0, b0, nullptr, pHh, pHs, 1, 0);

    // layer 1
    k_spmm1<<<nb_spmm, 256>>>(pHs, pX1h, pX1s);
    k_spmm2<<<nb_spmm, 256>>>(pX1s, pHh, pX2h);
    k_gemm<<<nb_gemm, 128>>>(pHh, pX1h, pX2h, W1, b1, nullptr, pHh, pHs, 1, 0);

    // layer 2 (no relu, fp32 out for pooling)
    k_spmm1<<<nb_spmm, 256>>>(pHs, pX1h, pX1s);
    k_spmm2<<<nb_spmm, 256>>>(pX1s, pHh, pX2h);
    k_gemm<<<nb_gemm, 128>>>(pHh, pX1h, pX2h, W2, b2, pH1, nullptr, nullptr, 0, 1);

    // readout
    k_bounds<<<1, 64>>>(gids);
    k_pool<<<NG, 256>>>(pH1);
    k_mlp<<<1, 1024>>>(M0w, M0b, M1w, M1b, M2w, M2b, out);
}

// round 4
// speedup vs baseline: 2.2041x; 1.0892x over previous
#include <cuda_runtime.h>
#include <cuda_fp16.h>
#include <math.h>
#include <stdint.h>

#define NN 100000
#define NE 1600000
#define NG 32
#define DH 64

// ---------------- scratch (device globals; no allocation allowed) -------------
__device__ int    g_deg[NN];
__device__ float  g_dinv[NN];
__device__ int    g_rowptr[NN + 1];
__device__ int    g_cursor[NN];
__device__ int    g_col[NE];
__device__ int    g_bsum[256];
__device__ __half g_hh[NN * DH];    // fp16 unscaled features (X0 for GEMM, z for spmm2)
__device__ __half g_hs[NN * DH];    // fp16 dinv-scaled features (gather operand)
__device__ __half g_x1h[NN * DH];   // fp16 X1 (for GEMM)
__device__ __half g_x1s[NN * DH];   // fp16 dinv-scaled X1 (gather operand spmm2)
__device__ __half g_x2h[NN * DH];   // fp16 X2 (for GEMM)
__device__ float  g_H1[NN * DH];    // fp32 final-layer output (for pooling)
__device__ int    g_gbound[NG + 1];
__device__ float  g_hg[NG * DH];

// ---------------- mma helpers ----------------
__device__ __forceinline__ uint32_t smem_u32(const void* p) {
    return (uint32_t)__cvta_generic_to_shared(p);
}
__device__ __forceinline__ void ldmx4(uint32_t* r, uint32_t addr) {
    asm volatile("ldmatrix.sync.aligned.m8n8.x4.shared.b16 {%0,%1,%2,%3}, [%4];"
                 : "=r"(r[0]), "=r"(r[1]), "=r"(r[2]), "=r"(r[3]) : "r"(addr));
}
__device__ __forceinline__ void ldmx4t(uint32_t* r, uint32_t addr) {
    asm volatile("ldmatrix.sync.aligned.m8n8.x4.trans.shared.b16 {%0,%1,%2,%3}, [%4];"
                 : "=r"(r[0]), "=r"(r[1]), "=r"(r[2]), "=r"(r[3]) : "r"(addr));
}
__device__ __forceinline__ void mma16816(float* c, const uint32_t* a, const uint32_t* b) {
    asm volatile("mma.sync.aligned.m16n8k16.row.col.f32.f16.f16.f32 "
                 "{%0,%1,%2,%3}, {%4,%5,%6,%7}, {%8,%9}, {%0,%1,%2,%3};"
                 : "+f"(c[0]), "+f"(c[1]), "+f"(c[2]), "+f"(c[3])
                 : "r"(a[0]), "r"(a[1]), "r"(a[2]), "r"(a[3]), "r"(b[0]), "r"(b[1]));
}

// ---------------- degree / CSR build ----------------
__global__ void k_zero_deg() {
    int i = blockIdx.x * blockDim.x + threadIdx.x;
    if (i < NN) g_deg[i] = 0;
}

__global__ void k_hist(const int* __restrict__ dst) {
    int e = blockIdx.x * blockDim.x + threadIdx.x;
    if (e * 4 < NE) {
        int4 d = ((const int4*)dst)[e];
        atomicAdd(&g_deg[d.x], 1);
        atomicAdd(&g_deg[d.y], 1);
        atomicAdd(&g_deg[d.z], 1);
        atomicAdd(&g_deg[d.w], 1);
    }
}

__global__ void k_scan1() {
    __shared__ int s[1024];
    int tid = threadIdx.x;
    int i = blockIdx.x * 1024 + tid;
    int v = (i < NN) ? g_deg[i] : 0;
    s[tid] = v;
    __syncthreads();
    for (int off = 1; off < 1024; off <<= 1) {
        int t = (tid >= off) ? s[tid - off] : 0;
        __syncthreads();
        s[tid] += t;
        __syncthreads();
    }
    if (i < NN) g_rowptr[i] = s[tid] - v;
    if (tid == 1023) g_bsum[blockIdx.x] = s[1023];
}

__global__ void k_scan2(int nb) {
    __shared__ int s[128];
    int tid = threadIdx.x;
    int v = (tid < nb) ? g_bsum[tid] : 0;
    s[tid] = v;
    __syncthreads();
    for (int off = 1; off < 128; off <<= 1) {
        int t = (tid >= off) ? s[tid - off] : 0;
        __syncthreads();
        s[tid] += t;
        __syncthreads();
    }
    if (tid < nb) g_bsum[tid] = s[tid] - v;
    if (tid == 127) g_rowptr[NN] = s[127];
}

// scan3 + dinv fused
__global__ void k_scan3() {
    int i = blockIdx.x * blockDim.x + threadIdx.x;
    if (i < NN) {
        int r = g_rowptr[i] + g_bsum[i >> 10];
        g_rowptr[i] = r;
        g_cursor[i] = r;
        g_dinv[i] = rsqrtf(fmaxf((float)g_deg[i], 1.0f));
    }
}

__global__ void k_fill(const int* __restrict__ src, const int* __restrict__ dst) {
    int e = blockIdx.x * blockDim.x + threadIdx.x;
    if (e * 4 < NE) {
        int4 d = ((const int4*)dst)[e];
        int4 s = ((const int4*)src)[e];
        g_col[atomicAdd(&g_cursor[d.x], 1)] = s.x;
        g_col[atomicAdd(&g_cursor[d.y], 1)] = s.y;
        g_col[atomicAdd(&g_cursor[d.z], 1)] = s.z;
        g_col[atomicAdd(&g_cursor[d.w], 1)] = s.w;
    }
}

// ---------------- prescale (layer 0 only): hs = half(dinv.*x), hh = half(x) ---
__global__ void k_pre(const float* __restrict__ x) {
    int i = blockIdx.x * blockDim.x + threadIdx.x;   // half2 index
    if (i < NN * 32) {
        float2 v = ((const float2*)x)[i];
        float di = g_dinv[i >> 5];
        ((__half2*)g_hs)[i] = __floats2half2_rn(v.x * di, v.y * di);
        ((__half2*)g_hh)[i] = __floats2half2_rn(v.x, v.y);
    }
}

// ---------------- gather accumulate helper (8 fp32 accs from one uint4) -------
__device__ __forceinline__ void acc8(float* a, uint4 v) {
    float2 f0 = __half22float2(*(const __half2*)&v.x);
    float2 f1 = __half22float2(*(const __half2*)&v.y);
    float2 f2 = __half22float2(*(const __half2*)&v.z);
    float2 f3 = __half22float2(*(const __half2*)&v.w);
    a[0] += f0.x; a[1] += f0.y; a[2] += f1.x; a[3] += f1.y;
    a[4] += f2.x; a[5] += f2.y; a[6] += f3.x; a[7] += f3.y;
}

// ---------------- SpMM1: X1h = half(-dinv.*(A hs)); X1s = half(dinv.*X1) ------
// 8 lanes/node; edge loop unrolled x4 with batched col loads (MLP=4).
__global__ void k_spmm1(const __half* __restrict__ ys, __half* __restrict__ X1h,
                        __half* __restrict__ X1s) {
    int node = blockIdx.x * (blockDim.x >> 3) + (threadIdx.x >> 3);
    int lane = threadIdx.x & 7;
    if (node >= NN) return;
    int s = g_rowptr[node], e = g_rowptr[node + 1];
    const uint4* yp = (const uint4*)ys;
    float a[8] = {0.f, 0.f, 0.f, 0.f, 0.f, 0.f, 0.f, 0.f};
    int i = s;
    for (; i + 4 <= e; i += 4) {
        int c0 = g_col[i], c1 = g_col[i + 1], c2 = g_col[i + 2], c3 = g_col[i + 3];
        uint4 v0 = yp[c0 * 8 + lane];
        uint4 v1 = yp[c1 * 8 + lane];
        uint4 v2 = yp[c2 * 8 + lane];
        uint4 v3 = yp[c3 * 8 + lane];
        acc8(a, v0); acc8(a, v1); acc8(a, v2); acc8(a, v3);
    }
    for (; i < e; i++) {
        uint4 v = yp[g_col[i] * 8 + lane];
        acc8(a, v);
    }
    float di = g_dinv[node];
    float s1 = -di;
    float s2 = -di * di;
    uint4 w1, w2;
    *(__half2*)&w1.x = __floats2half2_rn(s1 * a[0], s1 * a[1]);
    *(__half2*)&w1.y = __floats2half2_rn(s1 * a[2], s1 * a[3]);
    *(__half2*)&w1.z = __floats2half2_rn(s1 * a[4], s1 * a[5]);
    *(__half2*)&w1.w = __floats2half2_rn(s1 * a[6], s1 * a[7]);
    *(__half2*)&w2.x = __floats2half2_rn(s2 * a[0], s2 * a[1]);
    *(__half2*)&w2.y = __floats2half2_rn(s2 * a[2], s2 * a[3]);
    *(__half2*)&w2.z = __floats2half2_rn(s2 * a[4], s2 * a[5]);
    *(__half2*)&w2.w = __floats2half2_rn(s2 * a[6], s2 * a[7]);
    ((uint4*)X1h)[node * 8 + lane] = w1;
    ((uint4*)X1s)[node * 8 + lane] = w2;
}

// ---------------- SpMM2: X2h = half(-2*dinv.*(A X1s) - hh) --------------------
__global__ void k_spmm2(const __half* __restrict__ x1s, const __half* __restrict__ z,
                        __half* __restrict__ X2h) {
    int node = blockIdx.x * (blockDim.x >> 3) + (threadIdx.x >> 3);
    int lane = threadIdx.x & 7;
    if (node >= NN) return;
    int s = g_rowptr[node], e = g_rowptr[node + 1];
    const uint4* yp = (const uint4*)x1s;
    float a[8] = {0.f, 0.f, 0.f, 0.f, 0.f, 0.f, 0.f, 0.f};
    int i = s;
    for (; i + 4 <= e; i += 4) {
        int c0 = g_col[i], c1 = g_col[i + 1], c2 = g_col[i + 2], c3 = g_col[i + 3];
        uint4 v0 = yp[c0 * 8 + lane];
        uint4 v1 = yp[c1 * 8 + lane];
        uint4 v2 = yp[c2 * 8 + lane];
        uint4 v3 = yp[c3 * 8 + lane];
        acc8(a, v0); acc8(a, v1); acc8(a, v2); acc8(a, v3);
    }
    for (; i < e; i++) {
        uint4 v = yp[g_col[i] * 8 + lane];
        acc8(a, v);
    }
    float m = -2.f * g_dinv[node];
    uint4 zv = ((const uint4*)z)[node * 8 + lane];
    float2 z0 = __half22float2(*(const __half2*)&zv.x);
    float2 z1 = __half22float2(*(const __half2*)&zv.y);
    float2 z2 = __half22float2(*(const __half2*)&zv.z);
    float2 z3 = __half22float2(*(const __half2*)&zv.w);
    uint4 w;
    *(__half2*)&w.x = __floats2half2_rn(m * a[0] - z0.x, m * a[1] - z0.y);
    *(__half2*)&w.y = __floats2half2_rn(m * a[2] - z1.x, m * a[3] - z1.y);
    *(__half2*)&w.z = __floats2half2_rn(m * a[4] - z2.x, m * a[5] - z2.y);
    *(__half2*)&w.w = __floats2half2_rn(m * a[6] - z3.x, m * a[7] - z3.y);
    ((uint4*)X2h)[node * 8 + lane] = w;
}

// ---------------- GEMM (HMMA): out = [X0|X1|X2] @ W + b -----------------------
__global__ void k_gemm(const __half* __restrict__ x0, const __half* __restrict__ x1,
                       const __half* __restrict__ x2,
                       const float* __restrict__ W, const float* __restrict__ bias,
                       float* __restrict__ outF, __half* __restrict__ outH,
                       __half* __restrict__ outS, int relu, int wf32) {
    __shared__ __align__(16) __half Xs[128 * 72];
    __shared__ __align__(16) __half Ws[64 * 72];
    int tid = threadIdx.x;
    int warp = tid >> 5, lane = tid & 31;
    int n0 = blockIdx.x * 128;

    float acc[2][8][4];
    #pragma unroll
    for (int tm = 0; tm < 2; tm++)
        #pragma unroll
        for (int nt = 0; nt < 8; nt++)
            #pragma unroll
            for (int q = 0; q < 4; q++) acc[tm][nt][q] = 0.f;

    const __half* xp[3] = {x0, x1, x2};
    for (int p = 0; p < 3; p++) {
        const __half* xc = xp[p];
        #pragma unroll
        for (int i = 0; i < 8; i++) {
            int li = i * 128 + tid;
            int row = li >> 3, c = li & 7;
            int gn = n0 + row;
            uint4 v = (gn < NN) ? ((const uint4*)xc)[gn * 8 + c]
                                : make_uint4(0u, 0u, 0u, 0u);
            *(uint4*)&Xs[row * 72 + c * 8] = v;
        }
        #pragma unroll
        for (int i = 0; i < 8; i++) {
            int li = i * 128 + tid;
            int row = li >> 4, c = li & 15;
            float4 w = ((const float4*)(W + p * 4096))[li];
            __half2 h01 = __floats2half2_rn(w.x, w.y);
            __half2 h23 = __floats2half2_rn(w.z, w.w);
            uint2 pk;
            pk.x = *(uint32_t*)&h01;
            pk.y = *(uint32_t*)&h23;
            *(uint2*)&Ws[row * 72 + c * 4] = pk;
        }
        __syncthreads();
        #pragma unroll
        for (int ks = 0; ks < 4; ks++) {
            int kb = ks * 16;
            uint32_t A[2][4];
            #pragma unroll
            for (int tm = 0; tm < 2; tm++) {
                int r = warp * 32 + tm * 16 + (lane & 15);
                ldmx4(A[tm], smem_u32(&Xs[r * 72 + kb + (lane >> 4) * 8]));
            }
            uint32_t B[8][2];
            #pragma unroll
            for (int g = 0; g < 4; g++) {
                uint32_t t[4];
                int krow = kb + (lane & 15);
                ldmx4t(t, smem_u32(&Ws[krow * 72 + g * 16 + (lane >> 4) * 8]));
                B[g * 2 + 0][0] = t[0]; B[g * 2 + 0][1] = t[1];
                B[g * 2 + 1][0] = t[2]; B[g * 2 + 1][1] = t[3];
            }
            #pragma unroll
            for (int tm = 0; tm < 2; tm++)
                #pragma unroll
                for (int nt = 0; nt < 8; nt++)
                    mma16816(acc[tm][nt], A[tm], B[nt]);
        }
        __syncthreads();
    }

    int col = 2 * (lane & 3);
    #pragma unroll
    for (int tm = 0; tm < 2; tm++) {
        #pragma unroll
        for (int hh = 0; hh < 2; hh++) {
            int node = n0 + warp * 32 + tm * 16 + (lane >> 2) + hh * 8;
            if (node >= NN) continue;
            float di = g_dinv[node];
            #pragma unroll
            for (int nt = 0; nt < 8; nt++) {
                int f = nt * 8 + col;
                float2 bv = *(const float2*)&bias[f];
                float v0 = acc[tm][nt][hh * 2 + 0] + bv.x;
                float v1 = acc[tm][nt][hh * 2 + 1] + bv.y;
                if (relu) { v0 = fmaxf(v0, 0.f); v1 = fmaxf(v1, 0.f); }
                if (wf32) {
                    *(float2*)&outF[node * DH + f] = make_float2(v0, v1);
                } else {
                    *(__half2*)&outH[node * DH + f] = __floats2half2_rn(v0, v1);
                    *(__half2*)&outS[node * DH + f] = __floats2half2_rn(v0 * di, v1 * di);
                }
            }
        }
    }
}

// ---------------- readout ----------------
__global__ void k_bounds(const int* __restrict__ gids) {
    int g = threadIdx.x;
    if (g > NG) return;
    int lo = 0, hi = NN;
    while (lo < hi) {
        int mid = (lo + hi) >> 1;
        if (gids[mid] < g) lo = mid + 1; else hi = mid;
    }
    g_gbound[g] = lo;
}

__global__ void k_pool(const float* __restrict__ h) {
    int g = blockIdx.x;
    int s = g_gbound[g], e = g_gbound[g + 1];
    int f = threadIdx.x & 63, r = threadIdx.x >> 6;
    float acc = 0.f;
    for (int n = s + r; n < e; n += 4) acc += h[n * DH + f];
    __shared__ float sm[256];
    sm[threadIdx.x] = acc;
    __syncthreads();
    if (r == 0) {
        float v = sm[f] + sm[64 + f] + sm[128 + f] + sm[192 + f];
        float cnt = (float)(e - s);
        g_hg[g * DH + f] = v / fmaxf(cnt, 1.f);
    }
}

__global__ void k_mlp(const float* __restrict__ M0w, const float* __restrict__ M0b,
                      const float* __restrict__ M1w, const float* __restrict__ M1b,
                      const float* __restrict__ M2w, const float* __restrict__ M2b,
                      float* __restrict__ out) {
    __shared__ float h0[NG * 64];
    __shared__ float h1[NG * 32];
    __shared__ float h2[NG * 16];
    int tid = threadIdx.x;
    for (int i = tid; i < NG * 64; i += blockDim.x) h0[i] = g_hg[i];
    __syncthreads();
    if (tid < NG * 32) {
        int g = tid >> 5, f = tid & 31;
        float a = M0b[f];
        #pragma unroll
        for (int k = 0; k < 64; k++) a += h0[g * 64 + k] * M0w[k * 32 + f];
        h1[tid] = fmaxf(a, 0.f);
    }
    __syncthreads();
    if (tid < NG * 16) {
        int g = tid >> 4, f = tid & 15;
        float a = M1b[f];
        #pragma unroll
        for (int k = 0; k < 32; k++) a += h1[g * 32 + k] * M1w[k * 16 + f];
        h2[tid] = fmaxf(a, 0.f);
    }
    __syncthreads();
    if (tid < NG * 3) {
        int g = tid / 3, f = tid % 3;
        float a = M2b[f];
        #pragma unroll
        for (int k = 0; k < 16; k++) a += h2[g * 16 + k] * M2w[k * 3 + f];
        out[tid] = a;
    }
}

// ---------------- launch ----------------
extern "C" void kernel_launch(void* const* d_in, const int* in_sizes, int n_in,
                              void* d_out, int out_size) {
    const float* h    = (const float*)d_in[0];
    const int*   src  = (const int*)d_in[1];
    const int*   dst  = (const int*)d_in[2];
    const int*   gids = (const int*)d_in[3];
    const float* W0   = (const float*)d_in[4];
    const float* b0   = (const float*)d_in[5];
    const float* W1   = (const float*)d_in[6];
    const float* b1   = (const float*)d_in[7];
    const float* W2   = (const float*)d_in[8];
    const float* b2   = (const float*)d_in[9];
    const float* M0w  = (const float*)d_in[10];
    const float* M0b  = (const float*)d_in[11];
    const float* M1w  = (const float*)d_in[12];
    const float* M1b  = (const float*)d_in[13];
    const float* M2w  = (const float*)d_in[14];
    const float* M2b  = (const float*)d_in[15];
    float* out = (float*)d_out;

    float *pH1;
    __half *pHh, *pHs, *pX1h, *pX1s, *pX2h;
    cudaGetSymbolAddress((void**)&pH1, g_H1);
    cudaGetSymbolAddress((void**)&pHh, g_hh);
    cudaGetSymbolAddress((void**)&pHs, g_hs);
    cudaGetSymbolAddress((void**)&pX1h, g_x1h);
    cudaGetSymbolAddress((void**)&pX1s, g_x1s);
    cudaGetSymbolAddress((void**)&pX2h, g_x2h);

    const int nb_n = (NN + 255) / 256;
    const int nb_e4 = (NE / 4 + 255) / 256;
    const int nb_scan = (NN + 1023) / 1024;
    const int nb_spmm = (NN + 31) / 32;
    const int nb_gemm = (NN + 127) / 128;
    const int nb_pre = (NN * 32 + 255) / 256;

    // CSR build
    k_zero_deg<<<nb_n, 256>>>();
    k_hist<<<nb_e4, 256>>>(dst);
    k_scan1<<<nb_scan, 1024>>>();
    k_scan2<<<1, 128>>>(nb_scan);
    k_scan3<<<nb_n, 256>>>();
    k_fill<<<nb_e4, 256>>>(src, dst);

    // layer 0
    k_pre<<<nb_pre, 256>>>(h);
    k_spmm1<<<nb_spmm, 256>>>(pHs, pX1h, pX1s);
    k_spmm2<<<nb_spmm, 256>>>(pX1s, pHh, pX2h);
    k_gemm<<<nb_gemm, 128>>>(pHh, pX1h, pX2h, W0, b0, nullptr, pHh, pHs, 1, 0);

    // layer 1
    k_spmm1<<<nb_spmm, 256>>>(pHs, pX1h, pX1s);
    k_spmm2<<<nb_spmm, 256>>>(pX1s, pHh, pX2h);
    k_gemm<<<nb_gemm, 128>>>(pHh, pX1h, pX2h, W1, b1, nullptr, pHh, pHs, 1, 0);

    // layer 2 (no relu, fp32 out for pooling)
    k_spmm1<<<nb_spmm, 256>>>(pHs, pX1h, pX1s);
    k_spmm2<<<nb_spmm, 256>>>(pX1s, pHh, pX2h);
    k_gemm<<<nb_gemm, 128>>>(pHh, pX1h, pX2h, W2, b2, pH1, nullptr, nullptr, 0, 1);

    // readout
    k_bounds<<<1, 64>>>(gids);
    k_pool<<<NG, 256>>>(pH1);
    k_mlp<<<1, 1024>>>(M0w, M0b, M1w, M1b, M2w, M2b, out);
}

// round 5
// speedup vs baseline: 2.4148x; 1.0956x over previous
#include <cuda_runtime.h>
#include <cuda_fp16.h>
#include <math.h>
#include <stdint.h>

#define NN 100000
#define NE 1600000
#define NG 32
#define DH 64
#define SCAN_NB 98

typedef unsigned long long ull;

// ---------------- scratch (device globals; no allocation allowed) -------------
__device__ int    g_deg[NN];
__device__ float  g_dinv[NN];
__device__ int    g_rowptr[NN + 1];
__device__ int    g_cursor[NN];
__device__ int    g_col[NE];
__device__ ull    g_state[SCAN_NB];
__device__ __half g_hh[NN * DH];    // fp16 unscaled features
__device__ __half g_hs[NN * DH];    // fp16 dinv-scaled features (gather operand)
__device__ __half g_x1h[NN * DH];   // fp16 X1 (for GEMM)
__device__ __half g_x1s[NN * DH];   // fp16 dinv-scaled X1
__device__ __half g_x2h[NN * DH];   // fp16 X2 (for GEMM)
__device__ float  g_hg[NG * DH];

// ---------------- mma helpers ----------------
__device__ __forceinline__ uint32_t smem_u32(const void* p) {
    return (uint32_t)__cvta_generic_to_shared(p);
}
__device__ __forceinline__ void ldmx4(uint32_t* r, uint32_t addr) {
    asm volatile("ldmatrix.sync.aligned.m8n8.x4.shared.b16 {%0,%1,%2,%3}, [%4];"
                 : "=r"(r[0]), "=r"(r[1]), "=r"(r[2]), "=r"(r[3]) : "r"(addr));
}
__device__ __forceinline__ void ldmx4t(uint32_t* r, uint32_t addr) {
    asm volatile("ldmatrix.sync.aligned.m8n8.x4.trans.shared.b16 {%0,%1,%2,%3}, [%4];"
                 : "=r"(r[0]), "=r"(r[1]), "=r"(r[2]), "=r"(r[3]) : "r"(addr));
}
__device__ __forceinline__ void mma16816(float* c, const uint32_t* a, const uint32_t* b) {
    asm volatile("mma.sync.aligned.m16n8k16.row.col.f32.f16.f16.f32 "
                 "{%0,%1,%2,%3}, {%4,%5,%6,%7}, {%8,%9}, {%0,%1,%2,%3};"
                 : "+f"(c[0]), "+f"(c[1]), "+f"(c[2]), "+f"(c[3])
                 : "r"(a[0]), "r"(a[1]), "r"(a[2]), "r"(a[3]), "r"(b[0]), "r"(b[1]));
}

// ---------------- CSR build ----------------
__global__ void k_zero() {
    int i = blockIdx.x * blockDim.x + threadIdx.x;
    if (i < NN) g_deg[i] = 0;
    if (i < SCAN_NB) g_state[i] = 0ull;
}

__global__ void k_hist(const int* __restrict__ dst) {
    int e = blockIdx.x * blockDim.x + threadIdx.x;
    if (e * 4 < NE) {
        int4 d = ((const int4*)dst)[e];
        atomicAdd(&g_deg[d.x], 1);
        atomicAdd(&g_deg[d.y], 1);
        atomicAdd(&g_deg[d.z], 1);
        atomicAdd(&g_deg[d.w], 1);
    }
}

// single-pass scan: 98 blocks (all resident on 148 SMs -> spin is safe).
// Produces rowptr (exclusive), cursor copy, dinv, rowptr[NN].
__global__ void k_scan() {
    int tid = threadIdx.x, bid = blockIdx.x;
    int i = bid * 1024 + tid;
    int deg = (i < NN) ? g_deg[i] : 0;
    int lane = tid & 31, wid = tid >> 5;

    // warp inclusive scan
    int incl = deg;
    #pragma unroll
    for (int o = 1; o < 32; o <<= 1) {
        int t = __shfl_up_sync(0xFFFFFFFFu, incl, o);
        if (lane >= o) incl += t;
    }
    __shared__ int wsum[32];
    if (lane == 31) wsum[wid] = incl;
    __syncthreads();
    if (wid == 0) {
        int v = wsum[lane];
        int s = v;
        #pragma unroll
        for (int o = 1; o < 32; o <<= 1) {
            int t = __shfl_up_sync(0xFFFFFFFFu, s, o);
            if (lane >= o) s += t;
        }
        wsum[lane] = s - v;   // exclusive warp base
    }
    __syncthreads();
    int excl = incl - deg + wsum[wid];

    __shared__ int btotal;
    if (tid == 1023) btotal = excl + deg;
    __syncthreads();
    if (tid == 0) {
        __threadfence();
        atomicExch(&g_state[bid], ((ull)btotal) | (1ull << 40));
    }
    // gather all block aggregates
    __shared__ int aggs[SCAN_NB];
    if (tid < SCAN_NB) {
        ull v;
        do { v = atomicAdd(&g_state[tid], 0ull); } while (!(v >> 40));
        aggs[tid] = (int)(v & 0xFFFFFFFFull);
    }
    __syncthreads();
    __shared__ int sbase, stotal;
    if (tid == 0) {
        int b = 0, tot = 0;
        #pragma unroll 2
        for (int j = 0; j < SCAN_NB; j++) {
            if (j < bid) b += aggs[j];
            tot += aggs[j];
        }
        sbase = b; stotal = tot;
    }
    __syncthreads();
    if (i < NN) {
        int r = sbase + excl;
        g_rowptr[i] = r;
        g_cursor[i] = r;
        g_dinv[i] = rsqrtf(fmaxf((float)deg, 1.0f));
    }
    if (bid == SCAN_NB - 1 && tid == 0) g_rowptr[NN] = stotal;
}

__global__ void k_fill(const int* __restrict__ src, const int* __restrict__ dst) {
    int e = blockIdx.x * blockDim.x + threadIdx.x;
    if (e * 4 < NE) {
        int4 d = ((const int4*)dst)[e];
        int4 s = ((const int4*)src)[e];
        g_col[atomicAdd(&g_cursor[d.x], 1)] = s.x;
        g_col[atomicAdd(&g_cursor[d.y], 1)] = s.y;
        g_col[atomicAdd(&g_cursor[d.z], 1)] = s.z;
        g_col[atomicAdd(&g_cursor[d.w], 1)] = s.w;
    }
}

// ---------------- prescale (layer 0): hs = half(dinv.*x), hh = half(x) --------
__global__ void k_pre(const float* __restrict__ x) {
    int i = blockIdx.x * blockDim.x + threadIdx.x;   // half2 index
    if (i < NN * 32) {
        float2 v = ((const float2*)x)[i];
        float di = g_dinv[i >> 5];
        ((__half2*)g_hs)[i] = __floats2half2_rn(v.x * di, v.y * di);
        ((__half2*)g_hh)[i] = __floats2half2_rn(v.x, v.y);
    }
}

// ---------------- gather accumulate helper ----------------
__device__ __forceinline__ void acc8(float* a, uint4 v) {
    float2 f0 = __half22float2(*(const __half2*)&v.x);
    float2 f1 = __half22float2(*(const __half2*)&v.y);
    float2 f2 = __half22float2(*(const __half2*)&v.z);
    float2 f3 = __half22float2(*(const __half2*)&v.w);
    a[0] += f0.x; a[1] += f0.y; a[2] += f1.x; a[3] += f1.y;
    a[4] += f2.x; a[5] += f2.y; a[6] += f3.x; a[7] += f3.y;
}

// ---------------- SpMM1: X1h = half(-dinv.*(A hs)); X1s = half(dinv.*X1) ------
__global__ void k_spmm1(const __half* __restrict__ ys, __half* __restrict__ X1h,
                        __half* __restrict__ X1s) {
    int node = blockIdx.x * (blockDim.x >> 3) + (threadIdx.x >> 3);
    int lane = threadIdx.x & 7;
    if (node >= NN) return;
    int s = g_rowptr[node], e = g_rowptr[node + 1];
    const uint4* yp = (const uint4*)ys;
    float a[8] = {0.f, 0.f, 0.f, 0.f, 0.f, 0.f, 0.f, 0.f};
    int i = s;
    for (; i + 4 <= e; i += 4) {
        int c0 = g_col[i], c1 = g_col[i + 1], c2 = g_col[i + 2], c3 = g_col[i + 3];
        uint4 v0 = yp[c0 * 8 + lane];
        uint4 v1 = yp[c1 * 8 + lane];
        uint4 v2 = yp[c2 * 8 + lane];
        uint4 v3 = yp[c3 * 8 + lane];
        acc8(a, v0); acc8(a, v1); acc8(a, v2); acc8(a, v3);
    }
    for (; i < e; i++) {
        uint4 v = yp[g_col[i] * 8 + lane];
        acc8(a, v);
    }
    float di = g_dinv[node];
    float s1 = -di;
    float s2 = -di * di;
    uint4 w1, w2;
    *(__half2*)&w1.x = __floats2half2_rn(s1 * a[0], s1 * a[1]);
    *(__half2*)&w1.y = __floats2half2_rn(s1 * a[2], s1 * a[3]);
    *(__half2*)&w1.z = __floats2half2_rn(s1 * a[4], s1 * a[5]);
    *(__half2*)&w1.w = __floats2half2_rn(s1 * a[6], s1 * a[7]);
    *(__half2*)&w2.x = __floats2half2_rn(s2 * a[0], s2 * a[1]);
    *(__half2*)&w2.y = __floats2half2_rn(s2 * a[2], s2 * a[3]);
    *(__half2*)&w2.z = __floats2half2_rn(s2 * a[4], s2 * a[5]);
    *(__half2*)&w2.w = __floats2half2_rn(s2 * a[6], s2 * a[7]);
    ((uint4*)X1h)[node * 8 + lane] = w1;
    ((uint4*)X1s)[node * 8 + lane] = w2;
}

// ---------------- SpMM2: X2h = half(-2*dinv.*(A X1s) - hh) --------------------
__global__ void k_spmm2(const __half* __restrict__ x1s, const __half* __restrict__ z,
                        __half* __restrict__ X2h) {
    int node = blockIdx.x * (blockDim.x >> 3) + (threadIdx.x >> 3);
    int lane = threadIdx.x & 7;
    if (node >= NN) return;
    int s = g_rowptr[node], e = g_rowptr[node + 1];
    const uint4* yp = (const uint4*)x1s;
    float a[8] = {0.f, 0.f, 0.f, 0.f, 0.f, 0.f, 0.f, 0.f};
    int i = s;
    for (; i + 4 <= e; i += 4) {
        int c0 = g_col[i], c1 = g_col[i + 1], c2 = g_col[i + 2], c3 = g_col[i + 3];
        uint4 v0 = yp[c0 * 8 + lane];
        uint4 v1 = yp[c1 * 8 + lane];
        uint4 v2 = yp[c2 * 8 + lane];
        uint4 v3 = yp[c3 * 8 + lane];
        acc8(a, v0); acc8(a, v1); acc8(a, v2); acc8(a, v3);
    }
    for (; i < e; i++) {
        uint4 v = yp[g_col[i] * 8 + lane];
        acc8(a, v);
    }
    float m = -2.f * g_dinv[node];
    uint4 zv = ((const uint4*)z)[node * 8 + lane];
    float2 z0 = __half22float2(*(const __half2*)&zv.x);
    float2 z1 = __half22float2(*(const __half2*)&zv.y);
    float2 z2 = __half22float2(*(const __half2*)&zv.z);
    float2 z3 = __half22float2(*(const __half2*)&zv.w);
    uint4 w;
    *(__half2*)&w.x = __floats2half2_rn(m * a[0] - z0.x, m * a[1] - z0.y);
    *(__half2*)&w.y = __floats2half2_rn(m * a[2] - z1.x, m * a[3] - z1.y);
    *(__half2*)&w.z = __floats2half2_rn(m * a[4] - z2.x, m * a[5] - z2.y);
    *(__half2*)&w.w = __floats2half2_rn(m * a[6] - z3.x, m * a[7] - z3.y);
    ((uint4*)X2h)[node * 8 + lane] = w;
}

// ---------------- GEMM (HMMA): out = [X0|X1|X2] @ W + b -----------------------
// outH always written (fp16); outS (dinv-scaled) optional.
__global__ void k_gemm(const __half* __restrict__ x0, const __half* __restrict__ x1,
                       const __half* __restrict__ x2,
                       const float* __restrict__ W, const float* __restrict__ bias,
                       __half* __restrict__ outH, __half* __restrict__ outS, int relu) {
    __shared__ __align__(16) __half Xs[128 * 72];
    __shared__ __align__(16) __half Ws[64 * 72];
    int tid = threadIdx.x;
    int warp = tid >> 5, lane = tid & 31;
    int n0 = blockIdx.x * 128;

    float acc[2][8][4];
    #pragma unroll
    for (int tm = 0; tm < 2; tm++)
        #pragma unroll
        for (int nt = 0; nt < 8; nt++)
            #pragma unroll
            for (int q = 0; q < 4; q++) acc[tm][nt][q] = 0.f;

    const __half* xp[3] = {x0, x1, x2};
    for (int p = 0; p < 3; p++) {
        const __half* xc = xp[p];
        #pragma unroll
        for (int i = 0; i < 8; i++) {
            int li = i * 128 + tid;
            int row = li >> 3, c = li & 7;
            int gn = n0 + row;
            uint4 v = (gn < NN) ? ((const uint4*)xc)[gn * 8 + c]
                                : make_uint4(0u, 0u, 0u, 0u);
            *(uint4*)&Xs[row * 72 + c * 8] = v;
        }
        #pragma unroll
        for (int i = 0; i < 8; i++) {
            int li = i * 128 + tid;
            int row = li >> 4, c = li & 15;
            float4 w = ((const float4*)(W + p * 4096))[li];
            __half2 h01 = __floats2half2_rn(w.x, w.y);
            __half2 h23 = __floats2half2_rn(w.z, w.w);
            uint2 pk;
            pk.x = *(uint32_t*)&h01;
            pk.y = *(uint32_t*)&h23;
            *(uint2*)&Ws[row * 72 + c * 4] = pk;
        }
        __syncthreads();
        #pragma unroll
        for (int ks = 0; ks < 4; ks++) {
            int kb = ks * 16;
            uint32_t A[2][4];
            #pragma unroll
            for (int tm = 0; tm < 2; tm++) {
                int r = warp * 32 + tm * 16 + (lane & 15);
                ldmx4(A[tm], smem_u32(&Xs[r * 72 + kb + (lane >> 4) * 8]));
            }
            uint32_t B[8][2];
            #pragma unroll
            for (int g = 0; g < 4; g++) {
                uint32_t t[4];
                int krow = kb + (lane & 15);
                ldmx4t(t, smem_u32(&Ws[krow * 72 + g * 16 + (lane >> 4) * 8]));
                B[g * 2 + 0][0] = t[0]; B[g * 2 + 0][1] = t[1];
                B[g * 2 + 1][0] = t[2]; B[g * 2 + 1][1] = t[3];
            }
            #pragma unroll
            for (int tm = 0; tm < 2; tm++)
                #pragma unroll
                for (int nt = 0; nt < 8; nt++)
                    mma16816(acc[tm][nt], A[tm], B[nt]);
        }
        __syncthreads();
    }

    int col = 2 * (lane & 3);
    #pragma unroll
    for (int tm = 0; tm < 2; tm++) {
        #pragma unroll
        for (int hh = 0; hh < 2; hh++) {
            int node = n0 + warp * 32 + tm * 16 + (lane >> 2) + hh * 8;
            if (node >= NN) continue;
            float di = g_dinv[node];
            #pragma unroll
            for (int nt = 0; nt < 8; nt++) {
                int f = nt * 8 + col;
                float2 bv = *(const float2*)&bias[f];
                float v0 = acc[tm][nt][hh * 2 + 0] + bv.x;
                float v1 = acc[tm][nt][hh * 2 + 1] + bv.y;
                if (relu) { v0 = fmaxf(v0, 0.f); v1 = fmaxf(v1, 0.f); }
                *(__half2*)&outH[node * DH + f] = __floats2half2_rn(v0, v1);
                if (outS)
                    *(__half2*)&outS[node * DH + f] = __floats2half2_rn(v0 * di, v1 * di);
            }
        }
    }
}

// ---------------- readout: pool (bounds fused) --------------------------------
__global__ void k_pool(const __half* __restrict__ h, const int* __restrict__ gids) {
    int g = blockIdx.x;
    __shared__ int bnd[2];
    if (threadIdx.x < 2) {
        int target = g + threadIdx.x;
        int lo = 0, hi = NN;
        while (lo < hi) {
            int mid = (lo + hi) >> 1;
            if (gids[mid] < target) lo = mid + 1; else hi = mid;
        }
        bnd[threadIdx.x] = lo;
    }
    __syncthreads();
    int s = bnd[0], e = bnd[1];
    int f4 = threadIdx.x & 7;      // which uint4 (8 features)
    int way = threadIdx.x >> 3;    // 32 ways over nodes
    float a[8] = {0.f, 0.f, 0.f, 0.f, 0.f, 0.f, 0.f, 0.f};
    for (int n = s + way; n < e; n += 32) {
        uint4 v = ((const uint4*)(h + n * DH))[f4];
        acc8(a, v);
    }
    __shared__ float sm[32][64];
    #pragma unroll
    for (int j = 0; j < 8; j++) sm[way][f4 * 8 + j] = a[j];
    __syncthreads();
    if (threadIdx.x < 64) {
        float v = 0.f;
        #pragma unroll 8
        for (int w = 0; w < 32; w++) v += sm[w][threadIdx.x];
        float cnt = (float)(e - s);
        g_hg[g * DH + threadIdx.x] = v / fmaxf(cnt, 1.f);
    }
}

__global__ void k_mlp(const float* __restrict__ M0w, const float* __restrict__ M0b,
                      const float* __restrict__ M1w, const float* __restrict__ M1b,
                      const float* __restrict__ M2w, const float* __restrict__ M2b,
                      float* __restrict__ out) {
    __shared__ float h0[NG * 64];
    __shared__ float h1[NG * 32];
    __shared__ float h2[NG * 16];
    int tid = threadIdx.x;
    for (int i = tid; i < NG * 64; i += blockDim.x) h0[i] = g_hg[i];
    __syncthreads();
    if (tid < NG * 32) {
        int g = tid >> 5, f = tid & 31;
        float a = M0b[f];
        #pragma unroll
        for (int k = 0; k < 64; k++) a += h0[g * 64 + k] * M0w[k * 32 + f];
        h1[tid] = fmaxf(a, 0.f);
    }
    __syncthreads();
    if (tid < NG * 16) {
        int g = tid >> 4, f = tid & 15;
        float a = M1b[f];
        #pragma unroll
        for (int k = 0; k < 32; k++) a += h1[g * 32 + k] * M1w[k * 16 + f];
        h2[tid] = fmaxf(a, 0.f);
    }
    __syncthreads();
    if (tid < NG * 3) {
        int g = tid / 3, f = tid % 3;
        float a = M2b[f];
        #pragma unroll
        for (int k = 0; k < 16; k++) a += h2[g * 16 + k] * M2w[k * 3 + f];
        out[tid] = a;
    }
}

// ---------------- launch ----------------
extern "C" void kernel_launch(void* const* d_in, const int* in_sizes, int n_in,
                              void* d_out, int out_size) {
    const float* h    = (const float*)d_in[0];
    const int*   src  = (const int*)d_in[1];
    const int*   dst  = (const int*)d_in[2];
    const int*   gids = (const int*)d_in[3];
    const float* W0   = (const float*)d_in[4];
    const float* b0   = (const float*)d_in[5];
    const float* W1   = (const float*)d_in[6];
    const float* b1   = (const float*)d_in[7];
    const float* W2   = (const float*)d_in[8];
    const float* b2   = (const float*)d_in[9];
    const float* M0w  = (const float*)d_in[10];
    const float* M0b  = (const float*)d_in[11];
    const float* M1w  = (const float*)d_in[12];
    const float* M1b  = (const float*)d_in[13];
    const float* M2w  = (const float*)d_in[14];
    const float* M2b  = (const float*)d_in[15];
    float* out = (float*)d_out;

    __half *pHh, *pHs, *pX1h, *pX1s, *pX2h;
    cudaGetSymbolAddress((void**)&pHh, g_hh);
    cudaGetSymbolAddress((void**)&pHs, g_hs);
    cudaGetSymbolAddress((void**)&pX1h, g_x1h);
    cudaGetSymbolAddress((void**)&pX1s, g_x1s);
    cudaGetSymbolAddress((void**)&pX2h, g_x2h);

    const int nb_n = (NN + 255) / 256;
    const int nb_e4 = (NE / 4 + 255) / 256;
    const int nb_spmm = (NN + 31) / 32;
    const int nb_gemm = (NN + 127) / 128;
    const int nb_pre = (NN * 32 + 255) / 256;

    // CSR build (4 launches)
    k_zero<<<nb_n, 256>>>();
    k_hist<<<nb_e4, 256>>>(dst);
    k_scan<<<SCAN_NB, 1024>>>();
    k_fill<<<nb_e4, 256>>>(src, dst);

    // layer 0
    k_pre<<<nb_pre, 256>>>(h);
    k_spmm1<<<nb_spmm, 256>>>(pHs, pX1h, pX1s);
    k_spmm2<<<nb_spmm, 256>>>(pX1s, pHh, pX2h);
    k_gemm<<<nb_gemm, 128>>>(pHh, pX1h, pX2h, W0, b0, pHh, pHs, 1);

    // layer 1
    k_spmm1<<<nb_spmm, 256>>>(pHs, pX1h, pX1s);
    k_spmm2<<<nb_spmm, 256>>>(pX1s, pHh, pX2h);
    k_gemm<<<nb_gemm, 128>>>(pHh, pX1h, pX2h, W1, b1, pHh, pHs, 1);

    // layer 2 (no relu, fp16 out only)
    k_spmm1<<<nb_spmm, 256>>>(pHs, pX1h, pX1s);
    k_spmm2<<<nb_spmm, 256>>>(pX1s, pHh, pX2h);
    k_gemm<<<nb_gemm, 128>>>(pHh, pX1h, pX2h, W2, b2, pHh, nullptr, 0);

    // readout
    k_pool<<<NG, 256>>>(pHh, gids);
    k_mlp<<<1, 1024>>>(M0w, M0b, M1w, M1b, M2w, M2b, out);
}